// round 15
// baseline (speedup 1.0000x reference)
#include <cuda_runtime.h>
#include <cuda_fp16.h>
#include <math.h>
#include <stdint.h>

#define B_    4
#define S_    2048
#define DE    1024
#define NH    16
#define DH    64
#define BSROWS (B_ * S_)   // 8192

// scratch
__device__ float g_vp[(size_t)BSROWS * DE];
__device__ float2 g_rope[(size_t)S_ * 32];
__device__ __half g_qf2[(size_t)BSROWS * DE];
__device__ __half g_kf2[(size_t)BSROWS * DE];
__device__ __half g_vt2[(size_t)BSROWS * DE];
__device__ __half g_af[(size_t)BSROWS * 2 * DE];
__device__ __half g_wf[(size_t)DE * 2 * DE];

// ===========================================================================
// Helpers
// ===========================================================================
__device__ __forceinline__ uint32_t smem_u32(const void* p) {
    uint32_t a;
    asm("{ .reg .u64 t; cvta.to.shared.u64 t, %1; cvt.u32.u64 %0, t; }"
        : "=r"(a) : "l"(p));
    return a;
}
__device__ __forceinline__ void ldm4(uint32_t* r, uint32_t addr) {
    asm volatile("ldmatrix.sync.aligned.m8n8.x4.shared.b16 {%0,%1,%2,%3}, [%4];"
                 : "=r"(r[0]), "=r"(r[1]), "=r"(r[2]), "=r"(r[3]) : "r"(addr));
}
__device__ __forceinline__ void mma16816h(float* d, const uint32_t* a, const uint32_t* b) {
    asm volatile(
        "mma.sync.aligned.m16n8k16.row.col.f32.f16.f16.f32 "
        "{%0,%1,%2,%3}, {%4,%5,%6,%7}, {%8,%9}, {%0,%1,%2,%3};"
        : "+f"(d[0]), "+f"(d[1]), "+f"(d[2]), "+f"(d[3])
        : "r"(a[0]), "r"(a[1]), "r"(a[2]), "r"(a[3]), "r"(b[0]), "r"(b[1]));
}
__device__ __forceinline__ uint32_t pk_h2(float a, float b) {
    __half2 t = __floats2half2_rn(a, b);
    return *reinterpret_cast<uint32_t*>(&t);
}
__device__ __forceinline__ void cp16(uint32_t dst, const void* src) {
    asm volatile("cp.async.cg.shared.global [%0], [%1], 16;"
                 :: "r"(dst), "l"(src) : "memory");
}
#define CP_COMMIT() asm volatile("cp.async.commit_group;" ::: "memory")
#define CP_WAIT(N)  asm volatile("cp.async.wait_group %0;" :: "n"(N) : "memory")
__device__ __forceinline__ uint32_t swz64(uint32_t off) {
    return off ^ ((off >> 3) & 0x30);
}

// ===========================================================================
// prep_h: fp32 -> fp16
// ===========================================================================
__global__ __launch_bounds__(256) void prep_h(const float* __restrict__ s,
                                              __half* __restrict__ d, int n4) {
    int i = blockIdx.x * 256 + threadIdx.x;
    if (i >= n4) return;
    float4 v = ((const float4*)s)[i];
    ((uint2*)d)[i] = make_uint2(pk_h2(v.x, v.y), pk_h2(v.z, v.w));
}

// ===========================================================================
// fp16 GEMM core: 256(M) x 128(N) x 32(K) tiles, 8 warps as 4M x 2N,
// warp tile 64x64, cp.async 3-stage ring, SW64 swizzle.
// Stage: A (256x32) at 0 (16 KB), B (128x32) at 16384 (8 KB).
// ===========================================================================
#define GST_B 24576
#define GEMM_SMEM (3 * GST_B)   // 73,728 B

#define GEMM_PROLOG                                                            \
    extern __shared__ __align__(16) char gsm[];                                \
    const uint32_t smb = smem_u32(gsm);                                        \
    const int tid = threadIdx.x;                                               \
    const int wid = tid >> 5;                                                  \
    const int lane = tid & 31;                                                 \
    const int bm = blockIdx.y * 256;                                           \
    const int bn = blockIdx.x * 128;                                           \
    const int wm = (wid >> 1) * 64;                                            \
    const int wn = (wid & 1) * 64;                                             \
    const int nch = K / 32;                                                    \
    float acc[4][8][4];                                                        \
    _Pragma("unroll") for (int f = 0; f < 4; f++)                              \
        _Pragma("unroll") for (int n = 0; n < 8; n++)                          \
            _Pragma("unroll") for (int i = 0; i < 4; i++) acc[f][n][i] = 0.f;  \
    auto issue = [&](int c, int s) {                                           \
        const uint32_t base = smb + (uint32_t)s * GST_B;                       \
        _Pragma("unroll") for (int j = 0; j < 4; j++) {                        \
            int ch = tid + 256 * j;                                            \
            int r = ch >> 2, sg = ch & 3;                                      \
            cp16(base + swz64((uint32_t)r * 64 + sg * 16),                     \
                 A + (size_t)(bm + r) * K + c * 32 + sg * 8);                  \
        }                                                                      \
        _Pragma("unroll") for (int j = 0; j < 2; j++) {                        \
            int ch = tid + 256 * j;                                            \
            int r = ch >> 2, sg = ch & 3;                                      \
            cp16(base + 16384 + swz64((uint32_t)r * 64 + sg * 16),             \
                 Bm + (size_t)(bn + r) * K + c * 32 + sg * 8);                 \
        }                                                                      \
        CP_COMMIT();                                                           \
    };                                                                         \
    issue(0, 0);                                                               \
    if (nch > 1) issue(1, 1);                                                  \
    const int a_row = lane & 15;                                               \
    const int a_k8 = (lane >> 4) << 3;                                         \
    const int b_row = (lane & 7) + ((lane & 16) ? 8 : 0);                      \
    const int b_k8 = (lane & 8) ? 8 : 0;                                       \
    int st = 0;                                                                \
    for (int c = 0; c < nch; c++) {                                            \
        if (c + 2 < nch) { CP_WAIT(1); } else { CP_WAIT(0); }                  \
        __syncthreads();                                                       \
        if (c + 2 < nch) {                                                     \
            int ns = st + 2;                                                   \
            if (ns >= 3) ns -= 3;                                              \
            issue(c + 2, ns);                                                  \
        }                                                                      \
        const uint32_t kb = smb + (uint32_t)st * GST_B;                        \
        _Pragma("unroll") for (int ks = 0; ks < 32; ks += 16) {                \
            uint32_t afr[4][4];                                                \
            _Pragma("unroll") for (int f = 0; f < 4; f++)                      \
                ldm4(afr[f], kb + swz64((uint32_t)(wm + f * 16 + a_row) * 64 + \
                                        (uint32_t)(ks + a_k8) * 2));           \
            _Pragma("unroll") for (int g = 0; g < 4; g++) {                    \
                uint32_t t[4];                                                 \
                ldm4(t, kb + 16384 +                                           \
                        swz64((uint32_t)(wn + g * 16 + b_row) * 64 +           \
                              (uint32_t)(ks + b_k8) * 2));                     \
                uint32_t b0[2] = {t[0], t[1]}, b1[2] = {t[2], t[3]};           \
                _Pragma("unroll") for (int f = 0; f < 4; f++) {                \
                    mma16816h(acc[f][2 * g], afr[f], b0);                      \
                    mma16816h(acc[f][2 * g + 1], afr[f], b1);                  \
                }                                                              \
            }                                                                  \
        }                                                                      \
        if (++st == 3) st = 0;                                                 \
    }                                                                          \
    const int erow = lane >> 2;                                                \
    const int ecol = (lane & 3) * 2;

// fp32-output variant
__global__ __launch_bounds__(256) void gemm_hf(
    const __half* __restrict__ A, const __half* __restrict__ Bm,
    float* __restrict__ C, int M, int N, int K) {
    GEMM_PROLOG
#pragma unroll
    for (int f = 0; f < 4; f++) {
        const size_t r0 = (size_t)(bm + wm + f * 16 + erow);
#pragma unroll
        for (int n = 0; n < 8; n++) {
            const size_t cc = (size_t)(bn + wn + n * 8 + ecol);
            *(float2*)&C[r0 * N + cc] = make_float2(acc[f][n][0], acc[f][n][1]);
            *(float2*)&C[(r0 + 8) * N + cc] = make_float2(acc[f][n][2], acc[f][n][3]);
        }
    }
}

// fp16-output + fused RoPE variant (Q/K projections). qs = score prescale.
__global__ __launch_bounds__(256) void gemm_qk(
    const __half* __restrict__ A, const __half* __restrict__ Bm,
    __half* __restrict__ C, const float2* __restrict__ rope_t,
    float qs, int M, int N, int K) {
    GEMM_PROLOG
#pragma unroll
    for (int f = 0; f < 4; f++) {
        const size_t r0 = (size_t)(bm + wm + f * 16 + erow);
        const int pos0 = (int)(r0 & (S_ - 1));
#pragma unroll
        for (int n = 0; n < 8; n++) {
            const size_t cc = (size_t)(bn + wn + n * 8 + ecol);
            const int p = ((int)cc & 63) >> 1;
            float2 cs = rope_t[pos0 * 32 + p];
            float o1 = (acc[f][n][0] * cs.x - acc[f][n][1] * cs.y) * qs;
            float o2 = (acc[f][n][0] * cs.y + acc[f][n][1] * cs.x) * qs;
            *(uint32_t*)&C[r0 * N + cc] = pk_h2(o1, o2);
            cs = rope_t[(pos0 + 8) * 32 + p];
            o1 = (acc[f][n][2] * cs.x - acc[f][n][3] * cs.y) * qs;
            o2 = (acc[f][n][2] * cs.y + acc[f][n][3] * cs.x) * qs;
            *(uint32_t*)&C[(r0 + 8) * N + cc] = pk_h2(o1, o2);
        }
    }
}

// ===========================================================================
// RoPE table. sincos(x, SIN, COS) — sin first!
// ===========================================================================
__global__ void rope_table_kernel(float2* __restrict__ t) {
    int i = blockIdx.x * blockDim.x + threadIdx.x;
    int p = i & 31;
    int s = i >> 5;
    double inv = exp(-(double)p * (log(10000.0) / 32.0));
    double a = (double)s * inv;
    double sd, cd;
    sincos(a, &sd, &cd);
    t[i] = make_float2((float)cd, (float)sd);
}

// ===========================================================================
// Prep: V -> transposed fp16  vt[b][h][d][s]
// ===========================================================================
__global__ __launch_bounds__(256) void prep_vth(const float* __restrict__ vp,
                                                __half* __restrict__ vt) {
    __shared__ float sm[64][65];
    const int tid = threadIdx.x;
    const int st = blockIdx.x, h = blockIdx.y, b = blockIdx.z;

    for (int i = tid; i < 1024; i += 256) {
        int r = i >> 4;
        int f4 = (i & 15) * 4;
        float4 v = *(const float4*)&vp[(size_t)(b * S_ + st * 64 + r) * DE + h * DH + f4];
        sm[r][f4] = v.x; sm[r][f4 + 1] = v.y; sm[r][f4 + 2] = v.z; sm[r][f4 + 3] = v.w;
    }
    __syncthreads();

    const int d = tid >> 2;
    const int ks = (tid & 3) * 16;
    uint32_t pk[8];
#pragma unroll
    for (int j = 0; j < 8; j++)
        pk[j] = pk_h2(sm[ks + 2 * j][d], sm[ks + 2 * j + 1][d]);

    __half* dh = vt + ((size_t)((b * NH + h) * DH + d)) * S_ + st * 64 + ks;
    *(uint4*)&dh[0] = make_uint4(pk[0], pk[1], pk[2], pk[3]);
    *(uint4*)&dh[8] = make_uint4(pk[4], pk[5], pk[6], pk[7]);
}

// ===========================================================================
// fp16 tensor-core causal flash attention (round-14, PASS — unchanged)
// ===========================================================================
#define AP 72
#define STGE (128 * AP)
#define ATTN_SMEM (3 * STGE * 2)

__global__ __launch_bounds__(256) void attn_hf(
    const __half* __restrict__ qf, const __half* __restrict__ kf,
    const __half* __restrict__ vt, __half* __restrict__ af) {
    extern __shared__ __align__(16) __half sm[];

    const int tid = threadIdx.x;
    const int w = tid >> 5;
    const int lane = tid & 31;
    const int b = blockIdx.z, h = blockIdx.y;
    const int q0 = blockIdx.x * 128;
    const uint32_t smb = smem_u32(sm);
    const int nkt = 2 * blockIdx.x + 2;

    const __half* Kf = kf + (size_t)b * S_ * DE + h * DH;
    const __half* Vt = vt + (size_t)(b * NH + h) * DH * S_;

    const int cr = tid >> 3;
    const int csg = tid & 7;

    auto issue = [&](int k0, int s) {
        const uint32_t base = smb + (uint32_t)s * STGE * 2;
#pragma unroll
        for (int j = 0; j < 2; j++) {
            int r = cr + 32 * j;
            uint32_t dof = ((uint32_t)r * AP + csg * 8) * 2;
            cp16(base + dof, Kf + (size_t)(k0 + r) * DE + csg * 8);
            cp16(base + 64 * AP * 2 + dof, Vt + (size_t)r * S_ + k0 + csg * 8);
        }
        CP_COMMIT();
    };

    issue(0, 0);
    if (nkt > 1) issue(64, 1);

    {
        __half* qsm = sm + 2 * STGE;
        const __half* sh = qf + (size_t)(b * S_ + q0) * DE + h * DH;
#pragma unroll
        for (int j = 0; j < 4; j++) {
            int i = tid + 256 * j;
            int r = i >> 3, sg = i & 7;
            *(uint4*)&qsm[r * AP + sg * 8] = *(const uint4*)&sh[(size_t)r * DE + sg * 8];
        }
    }
    __syncthreads();

    uint32_t qfr[4][4];
    {
        const uint32_t qb = smb + 2 * STGE * 2;
        const int arow = w * 16 + (lane & 15);
        const int ak8 = (lane >> 4) << 3;
#pragma unroll
        for (int kc = 0; kc < 4; kc++)
            ldm4(qfr[kc], qb + (uint32_t)(arow * AP + kc * 16 + ak8) * 2);
    }
    __syncthreads();

    float oacc[8][4];
#pragma unroll
    for (int n = 0; n < 8; n++)
#pragma unroll
        for (int i = 0; i < 4; i++) oacc[n][i] = 0.f;
    float m0 = -1e30f, m1 = -1e30f, l0 = 0.f, l1 = 0.f;

    const int row0 = q0 + w * 16 + (lane >> 2);
    const int brow = (lane & 7) + ((lane & 16) ? 8 : 0);
    const int bk8 = (lane & 8) ? 8 : 0;

    int bufsel = 0;
    for (int kt = 0; kt < nkt; kt++) {
        const int k0 = kt * 64;
        if (kt + 2 < nkt) { CP_WAIT(1); } else { CP_WAIT(0); }
        __syncthreads();
        if (kt + 2 < nkt) {
            int nb = bufsel + 2;
            if (nb >= 3) nb -= 3;
            issue(k0 + 128, nb);
        }

        const uint32_t kb = smb + (uint32_t)bufsel * STGE * 2;

        float sacc[8][4];
#pragma unroll
        for (int n = 0; n < 8; n++)
#pragma unroll
            for (int i = 0; i < 4; i++) sacc[n][i] = 0.f;

#pragma unroll
        for (int kc = 0; kc < 4; kc++)
#pragma unroll
            for (int g = 0; g < 4; g++) {
                uint32_t off = (uint32_t)((g * 16 + brow) * AP + kc * 16 + bk8) * 2;
                uint32_t t[4];
                ldm4(t, kb + off);
                uint32_t b0[2] = {t[0], t[1]}, b1[2] = {t[2], t[3]};
                mma16816h(sacc[2 * g], qfr[kc], b0);
                mma16816h(sacc[2 * g + 1], qfr[kc], b1);
            }

        if (kt >= nkt - 2) {
#pragma unroll
            for (int n = 0; n < 8; n++) {
                int col = k0 + n * 8 + (lane & 3) * 2;
                if (col > row0) sacc[n][0] = -1e30f;
                if (col + 1 > row0) sacc[n][1] = -1e30f;
                if (col > row0 + 8) sacc[n][2] = -1e30f;
                if (col + 1 > row0 + 8) sacc[n][3] = -1e30f;
            }
        }

        float mt0 = -1e30f, mt1 = -1e30f;
#pragma unroll
        for (int n = 0; n < 8; n++) {
            mt0 = fmaxf(mt0, fmaxf(sacc[n][0], sacc[n][1]));
            mt1 = fmaxf(mt1, fmaxf(sacc[n][2], sacc[n][3]));
        }
        mt0 = fmaxf(mt0, __shfl_xor_sync(0xffffffffu, mt0, 1));
        mt0 = fmaxf(mt0, __shfl_xor_sync(0xffffffffu, mt0, 2));
        mt1 = fmaxf(mt1, __shfl_xor_sync(0xffffffffu, mt1, 1));
        mt1 = fmaxf(mt1, __shfl_xor_sync(0xffffffffu, mt1, 2));

        float mn0 = fmaxf(m0, mt0), mn1 = fmaxf(m1, mt1);
        float a0 = __expf(m0 - mn0), a1 = __expf(m1 - mn1);
        m0 = mn0; m1 = mn1;

        float s0 = 0.f, s1 = 0.f;
#pragma unroll
        for (int n = 0; n < 8; n++) {
            sacc[n][0] = __expf(sacc[n][0] - mn0);
            sacc[n][1] = __expf(sacc[n][1] - mn0);
            sacc[n][2] = __expf(sacc[n][2] - mn1);
            sacc[n][3] = __expf(sacc[n][3] - mn1);
            s0 += sacc[n][0] + sacc[n][1];
            s1 += sacc[n][2] + sacc[n][3];
        }
        s0 += __shfl_xor_sync(0xffffffffu, s0, 1);
        s0 += __shfl_xor_sync(0xffffffffu, s0, 2);
        s1 += __shfl_xor_sync(0xffffffffu, s1, 1);
        s1 += __shfl_xor_sync(0xffffffffu, s1, 2);
        l0 = l0 * a0 + s0;
        l1 = l1 * a1 + s1;
#pragma unroll
        for (int n = 0; n < 8; n++) {
            oacc[n][0] *= a0; oacc[n][1] *= a0;
            oacc[n][2] *= a1; oacc[n][3] *= a1;
        }

#pragma unroll
        for (int kc = 0; kc < 4; kc++) {
            uint32_t pa[4];
            pa[0] = pk_h2(sacc[2 * kc][0], sacc[2 * kc][1]);
            pa[1] = pk_h2(sacc[2 * kc][2], sacc[2 * kc][3]);
            pa[2] = pk_h2(sacc[2 * kc + 1][0], sacc[2 * kc + 1][1]);
            pa[3] = pk_h2(sacc[2 * kc + 1][2], sacc[2 * kc + 1][3]);
#pragma unroll
            for (int g = 0; g < 4; g++) {
                uint32_t off = (uint32_t)((64 + g * 16 + brow) * AP + kc * 16 + bk8) * 2;
                uint32_t t[4];
                ldm4(t, kb + off);
                uint32_t b0[2] = {t[0], t[1]}, b1[2] = {t[2], t[3]};
                mma16816h(oacc[2 * g], pa, b0);
                mma16816h(oacc[2 * g + 1], pa, b1);
            }
        }

        if (++bufsel == 3) bufsel = 0;
    }

    const float inv0 = 1.0f / l0, inv1 = 1.0f / l1;
    const size_t gr0 = (size_t)(b * S_ + row0);
#pragma unroll
    for (int n = 0; n < 8; n++) {
        const size_t cc = (size_t)(h * DH + n * 8 + (lane & 3) * 2);
        *(uint32_t*)&af[gr0 * DE + cc] = pk_h2(oacc[n][0] * inv0, oacc[n][1] * inv0);
        *(uint32_t*)&af[(gr0 + 8) * DE + cc] = pk_h2(oacc[n][2] * inv1, oacc[n][3] * inv1);
    }
}

// ===========================================================================
extern "C" void kernel_launch(void* const* d_in, const int* in_sizes, int n_in,
                              void* d_out, int out_size) {
    const float* q  = (const float*)d_in[0];
    const float* k  = (const float*)d_in[1];
    const float* v  = (const float*)d_in[2];
    const float* Wq = (const float*)d_in[3];
    const float* Wk = (const float*)d_in[4];
    const float* Wv = (const float*)d_in[5];
    const float* Wo = (const float*)d_in[6];
    float* out = (float*)d_out;

    float* vp;
    float2* rope_t;
    __half *qf, *kf, *vt, *af, *wf;
    cudaGetSymbolAddress((void**)&vp, g_vp);
    cudaGetSymbolAddress((void**)&rope_t, g_rope);
    cudaGetSymbolAddress((void**)&qf, g_qf2);
    cudaGetSymbolAddress((void**)&kf, g_kf2);
    cudaGetSymbolAddress((void**)&vt, g_vt2);
    cudaGetSymbolAddress((void**)&af, g_af);
    cudaGetSymbolAddress((void**)&wf, g_wf);

    cudaFuncSetAttribute(attn_hf, cudaFuncAttributeMaxDynamicSharedMemorySize,
                         ATTN_SMEM);
    cudaFuncSetAttribute(gemm_hf, cudaFuncAttributeMaxDynamicSharedMemorySize,
                         GEMM_SMEM);
    cudaFuncSetAttribute(gemm_qk, cudaFuncAttributeMaxDynamicSharedMemorySize,
                         GEMM_SMEM);

    rope_table_kernel<<<(S_ * 32) / 256, 256>>>(rope_t);

    const int n_qk = BSROWS * 2 * DE;
    const int n_v  = BSROWS * DE;
    const int n_w2 = DE * 2 * DE;
    const int n_w1 = DE * DE;
    dim3 gq(DE / 128, BSROWS / 256);       // (8, 32)

    // Q projection (+ fused RoPE, prescale 1/32, fp16 out)
    prep_h<<<n_w2 / 1024, 256>>>(Wq, wf, n_w2 / 4);
    prep_h<<<n_qk / 1024, 256>>>(q, af, n_qk / 4);
    gemm_qk<<<gq, 256, GEMM_SMEM>>>(af, wf, qf, rope_t, 0.03125f, BSROWS, DE, 2 * DE);
    // K projection (+ fused RoPE, fp16 out)
    prep_h<<<n_w2 / 1024, 256>>>(Wk, wf, n_w2 / 4);
    prep_h<<<n_qk / 1024, 256>>>(k, af, n_qk / 4);
    gemm_qk<<<gq, 256, GEMM_SMEM>>>(af, wf, kf, rope_t, 1.0f, BSROWS, DE, 2 * DE);
    // V projection (fp32 out for transpose prep)
    prep_h<<<n_w1 / 1024, 256>>>(Wv, wf, n_w1 / 4);
    prep_h<<<n_v / 1024, 256>>>(v, af, n_v / 4);
    gemm_hf<<<gq, 256, GEMM_SMEM>>>(af, wf, vp, BSROWS, DE, DE);

    prep_vth<<<dim3(S_ / 64, NH, B_), 256>>>(vp, vt);

    attn_hf<<<dim3(S_ / 128, NH, B_), 256, ATTN_SMEM>>>(qf, kf, vt, af);

    // Output projection
    prep_h<<<n_w1 / 1024, 256>>>(Wo, wf, n_w1 / 4);
    gemm_hf<<<gq, 256, GEMM_SMEM>>>(af, wf, out, BSROWS, DE, DE);
}

// round 16
// speedup vs baseline: 1.0741x; 1.0741x over previous
#include <cuda_runtime.h>
#include <cuda_fp16.h>
#include <math.h>
#include <stdint.h>

#define B_    4
#define S_    2048
#define DE    1024
#define NH    16
#define DH    64
#define BSROWS (B_ * S_)   // 8192

// scratch
__device__ float g_vp[(size_t)BSROWS * DE];
__device__ float2 g_rope[(size_t)S_ * 32];
__device__ __half g_qf2[(size_t)BSROWS * DE];
__device__ __half g_kf2[(size_t)BSROWS * DE];
__device__ __half g_vt2[(size_t)BSROWS * DE];
__device__ __half g_af[(size_t)BSROWS * 2 * DE];
__device__ __half g_wf[(size_t)DE * 2 * DE];

// ===========================================================================
// Helpers
// ===========================================================================
__device__ __forceinline__ uint32_t smem_u32(const void* p) {
    uint32_t a;
    asm("{ .reg .u64 t; cvta.to.shared.u64 t, %1; cvt.u32.u64 %0, t; }"
        : "=r"(a) : "l"(p));
    return a;
}
__device__ __forceinline__ void ldm4(uint32_t* r, uint32_t addr) {
    asm volatile("ldmatrix.sync.aligned.m8n8.x4.shared.b16 {%0,%1,%2,%3}, [%4];"
                 : "=r"(r[0]), "=r"(r[1]), "=r"(r[2]), "=r"(r[3]) : "r"(addr));
}
__device__ __forceinline__ void mma16816h(float* d, const uint32_t* a, const uint32_t* b) {
    asm volatile(
        "mma.sync.aligned.m16n8k16.row.col.f32.f16.f16.f32 "
        "{%0,%1,%2,%3}, {%4,%5,%6,%7}, {%8,%9}, {%0,%1,%2,%3};"
        : "+f"(d[0]), "+f"(d[1]), "+f"(d[2]), "+f"(d[3])
        : "r"(a[0]), "r"(a[1]), "r"(a[2]), "r"(a[3]), "r"(b[0]), "r"(b[1]));
}
__device__ __forceinline__ uint32_t pk_h2(float a, float b) {
    __half2 t = __floats2half2_rn(a, b);
    return *reinterpret_cast<uint32_t*>(&t);
}
__device__ __forceinline__ void cp16(uint32_t dst, const void* src) {
    asm volatile("cp.async.cg.shared.global [%0], [%1], 16;"
                 :: "r"(dst), "l"(src) : "memory");
}
#define CP_COMMIT() asm volatile("cp.async.commit_group;" ::: "memory")
#define CP_WAIT(N)  asm volatile("cp.async.wait_group %0;" :: "n"(N) : "memory")
__device__ __forceinline__ uint32_t swz64(uint32_t off) {
    return off ^ ((off >> 3) & 0x30);
}

// ===========================================================================
// prep_h: fp32 -> fp16
// ===========================================================================
__global__ __launch_bounds__(256) void prep_h(const float* __restrict__ s,
                                              __half* __restrict__ d, int n4) {
    int i = blockIdx.x * 256 + threadIdx.x;
    if (i >= n4) return;
    float4 v = ((const float4*)s)[i];
    ((uint2*)d)[i] = make_uint2(pk_h2(v.x, v.y), pk_h2(v.z, v.w));
}

// ===========================================================================
// fp16 GEMM core (round-13/14 geometry: 128x128x32, warp 32x64, 2 CTAs/SM)
// ===========================================================================
#define HSTAGE_B 16384
#define GEMM_SMEM (3 * HSTAGE_B)   // 49,152 B

#define GEMM_PROLOG                                                            \
    extern __shared__ __align__(16) char gsm[];                                \
    const uint32_t smb = smem_u32(gsm);                                        \
    const int tid = threadIdx.x;                                               \
    const int wid = tid >> 5;                                                  \
    const int lane = tid & 31;                                                 \
    const int bm = blockIdx.y * 128;                                           \
    const int bn = blockIdx.x * 128;                                           \
    const int wm = (wid >> 1) * 32;                                            \
    const int wn = (wid & 1) * 64;                                             \
    const int nch = K / 32;                                                    \
    float acc[2][8][4];                                                        \
    _Pragma("unroll") for (int f = 0; f < 2; f++)                              \
        _Pragma("unroll") for (int n = 0; n < 8; n++)                          \
            _Pragma("unroll") for (int i = 0; i < 4; i++) acc[f][n][i] = 0.f;  \
    auto issue = [&](int c, int s) {                                           \
        const uint32_t base = smb + (uint32_t)s * HSTAGE_B;                    \
        _Pragma("unroll") for (int j = 0; j < 2; j++) {                        \
            int ch = tid + 256 * j;                                            \
            int r = ch >> 2, sg = ch & 3;                                      \
            uint32_t d = swz64((uint32_t)r * 64 + sg * 16);                    \
            cp16(base + d, A + (size_t)(bm + r) * K + c * 32 + sg * 8);        \
            cp16(base + 8192 + d, Bm + (size_t)(bn + r) * K + c * 32 + sg * 8);\
        }                                                                      \
        CP_COMMIT();                                                           \
    };                                                                         \
    issue(0, 0);                                                               \
    if (nch > 1) issue(1, 1);                                                  \
    const int a_row = lane & 15;                                               \
    const int a_k8 = (lane >> 4) << 3;                                         \
    const int b_row = (lane & 7) + ((lane & 16) ? 8 : 0);                      \
    const int b_k8 = (lane & 8) ? 8 : 0;                                       \
    int st = 0;                                                                \
    for (int c = 0; c < nch; c++) {                                            \
        if (c + 2 < nch) { CP_WAIT(1); } else { CP_WAIT(0); }                  \
        __syncthreads();                                                       \
        if (c + 2 < nch) {                                                     \
            int ns = st + 2;                                                   \
            if (ns >= 3) ns -= 3;                                              \
            issue(c + 2, ns);                                                  \
        }                                                                      \
        const uint32_t kb = smb + (uint32_t)st * HSTAGE_B;                     \
        _Pragma("unroll") for (int ks = 0; ks < 32; ks += 16) {                \
            uint32_t afr[2][4];                                                \
            _Pragma("unroll") for (int f = 0; f < 2; f++)                      \
                ldm4(afr[f], kb + swz64((uint32_t)(wm + f * 16 + a_row) * 64 + \
                                        (uint32_t)(ks + a_k8) * 2));           \
            _Pragma("unroll") for (int g = 0; g < 4; g++) {                    \
                uint32_t t[4];                                                 \
                ldm4(t, kb + 8192 +                                            \
                        swz64((uint32_t)(wn + g * 16 + b_row) * 64 +           \
                              (uint32_t)(ks + b_k8) * 2));                     \
                uint32_t b0[2] = {t[0], t[1]}, b1[2] = {t[2], t[3]};           \
                _Pragma("unroll") for (int f = 0; f < 2; f++) {                \
                    mma16816h(acc[f][2 * g], afr[f], b0);                      \
                    mma16816h(acc[f][2 * g + 1], afr[f], b1);                  \
                }                                                              \
            }                                                                  \
        }                                                                      \
        if (++st == 3) st = 0;                                                 \
    }                                                                          \
    const int erow = lane >> 2;                                                \
    const int ecol = (lane & 3) * 2;

// fp32-output variant
__global__ __launch_bounds__(256, 2) void gemm_hf(
    const __half* __restrict__ A, const __half* __restrict__ Bm,
    float* __restrict__ C, int M, int N, int K) {
    GEMM_PROLOG
#pragma unroll
    for (int f = 0; f < 2; f++) {
        const size_t r0 = (size_t)(bm + wm + f * 16 + erow);
#pragma unroll
        for (int n = 0; n < 8; n++) {
            const size_t cc = (size_t)(bn + wn + n * 8 + ecol);
            *(float2*)&C[r0 * N + cc] = make_float2(acc[f][n][0], acc[f][n][1]);
            *(float2*)&C[(r0 + 8) * N + cc] = make_float2(acc[f][n][2], acc[f][n][3]);
        }
    }
}

// fp16-output + fused RoPE variant (Q/K projections). qs = score prescale.
__global__ __launch_bounds__(256, 2) void gemm_qk(
    const __half* __restrict__ A, const __half* __restrict__ Bm,
    __half* __restrict__ C, const float2* __restrict__ rope_t,
    float qs, int M, int N, int K) {
    GEMM_PROLOG
#pragma unroll
    for (int f = 0; f < 2; f++) {
        const size_t r0 = (size_t)(bm + wm + f * 16 + erow);
        const int pos0 = (int)(r0 & (S_ - 1));
#pragma unroll
        for (int n = 0; n < 8; n++) {
            const size_t cc = (size_t)(bn + wn + n * 8 + ecol);
            const int p = ((int)cc & 63) >> 1;
            float2 cs = rope_t[pos0 * 32 + p];
            float o1 = (acc[f][n][0] * cs.x - acc[f][n][1] * cs.y) * qs;
            float o2 = (acc[f][n][0] * cs.y + acc[f][n][1] * cs.x) * qs;
            *(uint32_t*)&C[r0 * N + cc] = pk_h2(o1, o2);
            cs = rope_t[(pos0 + 8) * 32 + p];
            o1 = (acc[f][n][2] * cs.x - acc[f][n][3] * cs.y) * qs;
            o2 = (acc[f][n][2] * cs.y + acc[f][n][3] * cs.x) * qs;
            *(uint32_t*)&C[(r0 + 8) * N + cc] = pk_h2(o1, o2);
        }
    }
}

// ===========================================================================
// RoPE table. sincos(x, SIN, COS) — sin first!
// ===========================================================================
__global__ void rope_table_kernel(float2* __restrict__ t) {
    int i = blockIdx.x * blockDim.x + threadIdx.x;
    int p = i & 31;
    int s = i >> 5;
    double inv = exp(-(double)p * (log(10000.0) / 32.0));
    double a = (double)s * inv;
    double sd, cd;
    sincos(a, &sd, &cd);
    t[i] = make_float2((float)cd, (float)sd);
}

// ===========================================================================
// Prep: V -> transposed fp16  vt[b][h][d][s]
// ===========================================================================
__global__ __launch_bounds__(256) void prep_vth(const float* __restrict__ vp,
                                                __half* __restrict__ vt) {
    __shared__ float sm[64][65];
    const int tid = threadIdx.x;
    const int st = blockIdx.x, h = blockIdx.y, b = blockIdx.z;

    for (int i = tid; i < 1024; i += 256) {
        int r = i >> 4;
        int f4 = (i & 15) * 4;
        float4 v = *(const float4*)&vp[(size_t)(b * S_ + st * 64 + r) * DE + h * DH + f4];
        sm[r][f4] = v.x; sm[r][f4 + 1] = v.y; sm[r][f4 + 2] = v.z; sm[r][f4 + 3] = v.w;
    }
    __syncthreads();

    const int d = tid >> 2;
    const int ks = (tid & 3) * 16;
    uint32_t pk[8];
#pragma unroll
    for (int j = 0; j < 8; j++)
        pk[j] = pk_h2(sm[ks + 2 * j][d], sm[ks + 2 * j + 1][d]);

    __half* dh = vt + ((size_t)((b * NH + h) * DH + d)) * S_ + st * 64 + ks;
    *(uint4*)&dh[0] = make_uint4(pk[0], pk[1], pk[2], pk[3]);
    *(uint4*)&dh[8] = make_uint4(pk[4], pk[5], pk[6], pk[7]);
}

// ===========================================================================
// fp16 tensor-core causal flash attention (round-14, PASS — unchanged)
// ===========================================================================
#define AP 72
#define STGE (128 * AP)
#define ATTN_SMEM (3 * STGE * 2)

__global__ __launch_bounds__(256) void attn_hf(
    const __half* __restrict__ qf, const __half* __restrict__ kf,
    const __half* __restrict__ vt, __half* __restrict__ af) {
    extern __shared__ __align__(16) __half sm[];

    const int tid = threadIdx.x;
    const int w = tid >> 5;
    const int lane = tid & 31;
    const int b = blockIdx.z, h = blockIdx.y;
    const int q0 = blockIdx.x * 128;
    const uint32_t smb = smem_u32(sm);
    const int nkt = 2 * blockIdx.x + 2;

    const __half* Kf = kf + (size_t)b * S_ * DE + h * DH;
    const __half* Vt = vt + (size_t)(b * NH + h) * DH * S_;

    const int cr = tid >> 3;
    const int csg = tid & 7;

    auto issue = [&](int k0, int s) {
        const uint32_t base = smb + (uint32_t)s * STGE * 2;
#pragma unroll
        for (int j = 0; j < 2; j++) {
            int r = cr + 32 * j;
            uint32_t dof = ((uint32_t)r * AP + csg * 8) * 2;
            cp16(base + dof, Kf + (size_t)(k0 + r) * DE + csg * 8);
            cp16(base + 64 * AP * 2 + dof, Vt + (size_t)r * S_ + k0 + csg * 8);
        }
        CP_COMMIT();
    };

    issue(0, 0);
    if (nkt > 1) issue(64, 1);

    {
        __half* qsm = sm + 2 * STGE;
        const __half* sh = qf + (size_t)(b * S_ + q0) * DE + h * DH;
#pragma unroll
        for (int j = 0; j < 4; j++) {
            int i = tid + 256 * j;
            int r = i >> 3, sg = i & 7;
            *(uint4*)&qsm[r * AP + sg * 8] = *(const uint4*)&sh[(size_t)r * DE + sg * 8];
        }
    }
    __syncthreads();

    uint32_t qfr[4][4];
    {
        const uint32_t qb = smb + 2 * STGE * 2;
        const int arow = w * 16 + (lane & 15);
        const int ak8 = (lane >> 4) << 3;
#pragma unroll
        for (int kc = 0; kc < 4; kc++)
            ldm4(qfr[kc], qb + (uint32_t)(arow * AP + kc * 16 + ak8) * 2);
    }
    __syncthreads();

    float oacc[8][4];
#pragma unroll
    for (int n = 0; n < 8; n++)
#pragma unroll
        for (int i = 0; i < 4; i++) oacc[n][i] = 0.f;
    float m0 = -1e30f, m1 = -1e30f, l0 = 0.f, l1 = 0.f;

    const int row0 = q0 + w * 16 + (lane >> 2);
    const int brow = (lane & 7) + ((lane & 16) ? 8 : 0);
    const int bk8 = (lane & 8) ? 8 : 0;

    int bufsel = 0;
    for (int kt = 0; kt < nkt; kt++) {
        const int k0 = kt * 64;
        if (kt + 2 < nkt) { CP_WAIT(1); } else { CP_WAIT(0); }
        __syncthreads();
        if (kt + 2 < nkt) {
            int nb = bufsel + 2;
            if (nb >= 3) nb -= 3;
            issue(k0 + 128, nb);
        }

        const uint32_t kb = smb + (uint32_t)bufsel * STGE * 2;

        float sacc[8][4];
#pragma unroll
        for (int n = 0; n < 8; n++)
#pragma unroll
            for (int i = 0; i < 4; i++) sacc[n][i] = 0.f;

#pragma unroll
        for (int kc = 0; kc < 4; kc++)
#pragma unroll
            for (int g = 0; g < 4; g++) {
                uint32_t off = (uint32_t)((g * 16 + brow) * AP + kc * 16 + bk8) * 2;
                uint32_t t[4];
                ldm4(t, kb + off);
                uint32_t b0[2] = {t[0], t[1]}, b1[2] = {t[2], t[3]};
                mma16816h(sacc[2 * g], qfr[kc], b0);
                mma16816h(sacc[2 * g + 1], qfr[kc], b1);
            }

        if (kt >= nkt - 2) {
#pragma unroll
            for (int n = 0; n < 8; n++) {
                int col = k0 + n * 8 + (lane & 3) * 2;
                if (col > row0) sacc[n][0] = -1e30f;
                if (col + 1 > row0) sacc[n][1] = -1e30f;
                if (col > row0 + 8) sacc[n][2] = -1e30f;
                if (col + 1 > row0 + 8) sacc[n][3] = -1e30f;
            }
        }

        float mt0 = -1e30f, mt1 = -1e30f;
#pragma unroll
        for (int n = 0; n < 8; n++) {
            mt0 = fmaxf(mt0, fmaxf(sacc[n][0], sacc[n][1]));
            mt1 = fmaxf(mt1, fmaxf(sacc[n][2], sacc[n][3]));
        }
        mt0 = fmaxf(mt0, __shfl_xor_sync(0xffffffffu, mt0, 1));
        mt0 = fmaxf(mt0, __shfl_xor_sync(0xffffffffu, mt0, 2));
        mt1 = fmaxf(mt1, __shfl_xor_sync(0xffffffffu, mt1, 1));
        mt1 = fmaxf(mt1, __shfl_xor_sync(0xffffffffu, mt1, 2));

        float mn0 = fmaxf(m0, mt0), mn1 = fmaxf(m1, mt1);
        float a0 = __expf(m0 - mn0), a1 = __expf(m1 - mn1);
        m0 = mn0; m1 = mn1;

        float s0 = 0.f, s1 = 0.f;
#pragma unroll
        for (int n = 0; n < 8; n++) {
            sacc[n][0] = __expf(sacc[n][0] - mn0);
            sacc[n][1] = __expf(sacc[n][1] - mn0);
            sacc[n][2] = __expf(sacc[n][2] - mn1);
            sacc[n][3] = __expf(sacc[n][3] - mn1);
            s0 += sacc[n][0] + sacc[n][1];
            s1 += sacc[n][2] + sacc[n][3];
        }
        s0 += __shfl_xor_sync(0xffffffffu, s0, 1);
        s0 += __shfl_xor_sync(0xffffffffu, s0, 2);
        s1 += __shfl_xor_sync(0xffffffffu, s1, 1);
        s1 += __shfl_xor_sync(0xffffffffu, s1, 2);
        l0 = l0 * a0 + s0;
        l1 = l1 * a1 + s1;
#pragma unroll
        for (int n = 0; n < 8; n++) {
            oacc[n][0] *= a0; oacc[n][1] *= a0;
            oacc[n][2] *= a1; oacc[n][3] *= a1;
        }

#pragma unroll
        for (int kc = 0; kc < 4; kc++) {
            uint32_t pa[4];
            pa[0] = pk_h2(sacc[2 * kc][0], sacc[2 * kc][1]);
            pa[1] = pk_h2(sacc[2 * kc][2], sacc[2 * kc][3]);
            pa[2] = pk_h2(sacc[2 * kc + 1][0], sacc[2 * kc + 1][1]);
            pa[3] = pk_h2(sacc[2 * kc + 1][2], sacc[2 * kc + 1][3]);
#pragma unroll
            for (int g = 0; g < 4; g++) {
                uint32_t off = (uint32_t)((64 + g * 16 + brow) * AP + kc * 16 + bk8) * 2;
                uint32_t t[4];
                ldm4(t, kb + off);
                uint32_t b0[2] = {t[0], t[1]}, b1[2] = {t[2], t[3]};
                mma16816h(oacc[2 * g], pa, b0);
                mma16816h(oacc[2 * g + 1], pa, b1);
            }
        }

        if (++bufsel == 3) bufsel = 0;
    }

    const float inv0 = 1.0f / l0, inv1 = 1.0f / l1;
    const size_t gr0 = (size_t)(b * S_ + row0);
#pragma unroll
    for (int n = 0; n < 8; n++) {
        const size_t cc = (size_t)(h * DH + n * 8 + (lane & 3) * 2);
        *(uint32_t*)&af[gr0 * DE + cc] = pk_h2(oacc[n][0] * inv0, oacc[n][1] * inv0);
        *(uint32_t*)&af[(gr0 + 8) * DE + cc] = pk_h2(oacc[n][2] * inv1, oacc[n][3] * inv1);
    }
}

// ===========================================================================
extern "C" void kernel_launch(void* const* d_in, const int* in_sizes, int n_in,
                              void* d_out, int out_size) {
    const float* q  = (const float*)d_in[0];
    const float* k  = (const float*)d_in[1];
    const float* v  = (const float*)d_in[2];
    const float* Wq = (const float*)d_in[3];
    const float* Wk = (const float*)d_in[4];
    const float* Wv = (const float*)d_in[5];
    const float* Wo = (const float*)d_in[6];
    float* out = (float*)d_out;

    float* vp;
    float2* rope_t;
    __half *qf, *kf, *vt, *af, *wf;
    cudaGetSymbolAddress((void**)&vp, g_vp);
    cudaGetSymbolAddress((void**)&rope_t, g_rope);
    cudaGetSymbolAddress((void**)&qf, g_qf2);
    cudaGetSymbolAddress((void**)&kf, g_kf2);
    cudaGetSymbolAddress((void**)&vt, g_vt2);
    cudaGetSymbolAddress((void**)&af, g_af);
    cudaGetSymbolAddress((void**)&wf, g_wf);

    cudaFuncSetAttribute(attn_hf, cudaFuncAttributeMaxDynamicSharedMemorySize,
                         ATTN_SMEM);
    cudaFuncSetAttribute(gemm_hf, cudaFuncAttributeMaxDynamicSharedMemorySize,
                         GEMM_SMEM);
    cudaFuncSetAttribute(gemm_qk, cudaFuncAttributeMaxDynamicSharedMemorySize,
                         GEMM_SMEM);

    rope_table_kernel<<<(S_ * 32) / 256, 256>>>(rope_t);

    const int n_qk = BSROWS * 2 * DE;
    const int n_v  = BSROWS * DE;
    const int n_w2 = DE * 2 * DE;
    const int n_w1 = DE * DE;
    dim3 gq(DE / 128, BSROWS / 128);       // (8, 64)

    // Q projection (+ fused RoPE, prescale 1/32, fp16 out)
    prep_h<<<n_w2 / 1024, 256>>>(Wq, wf, n_w2 / 4);
    prep_h<<<n_qk / 1024, 256>>>(q, af, n_qk / 4);
    gemm_qk<<<gq, 256, GEMM_SMEM>>>(af, wf, qf, rope_t, 0.03125f, BSROWS, DE, 2 * DE);
    // K projection (+ fused RoPE, fp16 out)
    prep_h<<<n_w2 / 1024, 256>>>(Wk, wf, n_w2 / 4);
    prep_h<<<n_qk / 1024, 256>>>(k, af, n_qk / 4);
    gemm_qk<<<gq, 256, GEMM_SMEM>>>(af, wf, kf, rope_t, 1.0f, BSROWS, DE, 2 * DE);
    // V projection (fp32 out for transpose prep)
    prep_h<<<n_w1 / 1024, 256>>>(Wv, wf, n_w1 / 4);
    prep_h<<<n_v / 1024, 256>>>(v, af, n_v / 4);
    gemm_hf<<<gq, 256, GEMM_SMEM>>>(af, wf, vp, BSROWS, DE, DE);

    prep_vth<<<dim3(S_ / 64, NH, B_), 256>>>(vp, vt);

    attn_hf<<<dim3(S_ / 128, NH, B_), 256, ATTN_SMEM>>>(qf, kf, vt, af);

    // Output projection
    prep_h<<<n_w1 / 1024, 256>>>(Wo, wf, n_w1 / 4);
    gemm_hf<<<gq, 256, GEMM_SMEM>>>(af, wf, out, BSROWS, DE, DE);
}

// round 17
// speedup vs baseline: 1.1305x; 1.0525x over previous
#include <cuda_runtime.h>
#include <cuda_fp16.h>
#include <math.h>
#include <stdint.h>

#define B_    4
#define S_    2048
#define DE    1024
#define NH    16
#define DH    64
#define BSROWS (B_ * S_)   // 8192

// scratch
__device__ float g_vp[(size_t)BSROWS * DE];
__device__ float2 g_rope[(size_t)S_ * 32];
__device__ __half g_qf2[(size_t)BSROWS * DE];
__device__ __half g_kf2[(size_t)BSROWS * DE];
__device__ __half g_vt2[(size_t)BSROWS * DE];
__device__ __half g_af[(size_t)BSROWS * 2 * DE];
__device__ __half g_wf[(size_t)DE * 2 * DE];

// ===========================================================================
// Helpers
// ===========================================================================
__device__ __forceinline__ uint32_t smem_u32(const void* p) {
    uint32_t a;
    asm("{ .reg .u64 t; cvta.to.shared.u64 t, %1; cvt.u32.u64 %0, t; }"
        : "=r"(a) : "l"(p));
    return a;
}
__device__ __forceinline__ void ldm4(uint32_t* r, uint32_t addr) {
    asm volatile("ldmatrix.sync.aligned.m8n8.x4.shared.b16 {%0,%1,%2,%3}, [%4];"
                 : "=r"(r[0]), "=r"(r[1]), "=r"(r[2]), "=r"(r[3]) : "r"(addr));
}
__device__ __forceinline__ void mma16816h(float* d, const uint32_t* a, const uint32_t* b) {
    asm volatile(
        "mma.sync.aligned.m16n8k16.row.col.f32.f16.f16.f32 "
        "{%0,%1,%2,%3}, {%4,%5,%6,%7}, {%8,%9}, {%0,%1,%2,%3};"
        : "+f"(d[0]), "+f"(d[1]), "+f"(d[2]), "+f"(d[3])
        : "r"(a[0]), "r"(a[1]), "r"(a[2]), "r"(a[3]), "r"(b[0]), "r"(b[1]));
}
__device__ __forceinline__ uint32_t pk_h2(float a, float b) {
    __half2 t = __floats2half2_rn(a, b);
    return *reinterpret_cast<uint32_t*>(&t);
}
__device__ __forceinline__ void cp16(uint32_t dst, const void* src) {
    asm volatile("cp.async.cg.shared.global [%0], [%1], 16;"
                 :: "r"(dst), "l"(src) : "memory");
}
#define CP_COMMIT() asm volatile("cp.async.commit_group;" ::: "memory")
#define CP_WAIT(N)  asm volatile("cp.async.wait_group %0;" :: "n"(N) : "memory")
__device__ __forceinline__ uint32_t swz64(uint32_t off) {
    return off ^ ((off >> 3) & 0x30);
}
__device__ __forceinline__ uint32_t swz128(uint32_t off) {
    return off ^ ((off >> 3) & 0x70);
}

// ===========================================================================
// prep_h: fp32 -> fp16
// ===========================================================================
__global__ __launch_bounds__(256) void prep_h(const float* __restrict__ s,
                                              __half* __restrict__ d, int n4) {
    int i = blockIdx.x * 256 + threadIdx.x;
    if (i >= n4) return;
    float4 v = ((const float4*)s)[i];
    ((uint2*)d)[i] = make_uint2(pk_h2(v.x, v.y), pk_h2(v.z, v.w));
}

// ===========================================================================
// fp16 GEMM core: 128x128 tile, warp 32x64, K-chunk 64, SW128 swizzle,
// cp.async 3-stage ring (96 KB), 2 CTAs/SM.
// Stage: A (128x64) at 0 (16 KB), B (128x64) at 16384 (16 KB).
// ===========================================================================
#define HSTAGE_B 32768
#define GEMM_SMEM (3 * HSTAGE_B)   // 98,304 B

#define GEMM_PROLOG                                                            \
    extern __shared__ __align__(16) char gsm[];                                \
    const uint32_t smb = smem_u32(gsm);                                        \
    const int tid = threadIdx.x;                                               \
    const int wid = tid >> 5;                                                  \
    const int lane = tid & 31;                                                 \
    const int bm = blockIdx.y * 128;                                           \
    const int bn = blockIdx.x * 128;                                           \
    const int wm = (wid >> 1) * 32;                                            \
    const int wn = (wid & 1) * 64;                                             \
    const int nch = K / 64;                                                    \
    float acc[2][8][4];                                                        \
    _Pragma("unroll") for (int f = 0; f < 2; f++)                              \
        _Pragma("unroll") for (int n = 0; n < 8; n++)                          \
            _Pragma("unroll") for (int i = 0; i < 4; i++) acc[f][n][i] = 0.f;  \
    auto issue = [&](int c, int s) {                                           \
        const uint32_t base = smb + (uint32_t)s * HSTAGE_B;                    \
        _Pragma("unroll") for (int j = 0; j < 4; j++) {                        \
            int ch = tid + 256 * j;                                            \
            int r = ch >> 3, sg = ch & 7;                                      \
            uint32_t d = swz128((uint32_t)r * 128 + sg * 16);                  \
            cp16(base + d, A + (size_t)(bm + r) * K + c * 64 + sg * 8);        \
            cp16(base + 16384 + d, Bm + (size_t)(bn + r) * K + c * 64 + sg * 8);\
        }                                                                      \
        CP_COMMIT();                                                           \
    };                                                                         \
    issue(0, 0);                                                               \
    if (nch > 1) issue(1, 1);                                                  \
    const int a_row = lane & 15;                                               \
    const int a_k8 = (lane >> 4) << 3;                                         \
    const int b_row = (lane & 7) + ((lane & 16) ? 8 : 0);                      \
    const int b_k8 = (lane & 8) ? 8 : 0;                                       \
    int st = 0;                                                                \
    for (int c = 0; c < nch; c++) {                                            \
        if (c + 2 < nch) { CP_WAIT(1); } else { CP_WAIT(0); }                  \
        __syncthreads();                                                       \
        if (c + 2 < nch) {                                                     \
            int ns = st + 2;                                                   \
            if (ns >= 3) ns -= 3;                                              \
            issue(c + 2, ns);                                                  \
        }                                                                      \
        const uint32_t kb = smb + (uint32_t)st * HSTAGE_B;                     \
        _Pragma("unroll") for (int ks = 0; ks < 64; ks += 16) {                \
            uint32_t afr[2][4];                                                \
            _Pragma("unroll") for (int f = 0; f < 2; f++)                      \
                ldm4(afr[f], kb + swz128((uint32_t)(wm + f * 16 + a_row) * 128 +\
                                         (uint32_t)(ks + a_k8) * 2));          \
            _Pragma("unroll") for (int g = 0; g < 4; g++) {                    \
                uint32_t t[4];                                                 \
                ldm4(t, kb + 16384 +                                           \
                        swz128((uint32_t)(wn + g * 16 + b_row) * 128 +         \
                               (uint32_t)(ks + b_k8) * 2));                    \
                uint32_t b0[2] = {t[0], t[1]}, b1[2] = {t[2], t[3]};           \
                _Pragma("unroll") for (int f = 0; f < 2; f++) {                \
                    mma16816h(acc[f][2 * g], afr[f], b0);                      \
                    mma16816h(acc[f][2 * g + 1], afr[f], b1);                  \
                }                                                              \
            }                                                                  \
        }                                                                      \
        if (++st == 3) st = 0;                                                 \
    }                                                                          \
    const int erow = lane >> 2;                                                \
    const int ecol = (lane & 3) * 2;

// fp32-output variant
__global__ __launch_bounds__(256, 2) void gemm_hf(
    const __half* __restrict__ A, const __half* __restrict__ Bm,
    float* __restrict__ C, int M, int N, int K) {
    GEMM_PROLOG
#pragma unroll
    for (int f = 0; f < 2; f++) {
        const size_t r0 = (size_t)(bm + wm + f * 16 + erow);
#pragma unroll
        for (int n = 0; n < 8; n++) {
            const size_t cc = (size_t)(bn + wn + n * 8 + ecol);
            *(float2*)&C[r0 * N + cc] = make_float2(acc[f][n][0], acc[f][n][1]);
            *(float2*)&C[(r0 + 8) * N + cc] = make_float2(acc[f][n][2], acc[f][n][3]);
        }
    }
}

// fp16-output + fused RoPE variant (Q/K projections). qs = score prescale.
__global__ __launch_bounds__(256, 2) void gemm_qk(
    const __half* __restrict__ A, const __half* __restrict__ Bm,
    __half* __restrict__ C, const float2* __restrict__ rope_t,
    float qs, int M, int N, int K) {
    GEMM_PROLOG
#pragma unroll
    for (int f = 0; f < 2; f++) {
        const size_t r0 = (size_t)(bm + wm + f * 16 + erow);
        const int pos0 = (int)(r0 & (S_ - 1));
#pragma unroll
        for (int n = 0; n < 8; n++) {
            const size_t cc = (size_t)(bn + wn + n * 8 + ecol);
            const int p = ((int)cc & 63) >> 1;
            float2 cs = rope_t[pos0 * 32 + p];
            float o1 = (acc[f][n][0] * cs.x - acc[f][n][1] * cs.y) * qs;
            float o2 = (acc[f][n][0] * cs.y + acc[f][n][1] * cs.x) * qs;
            *(uint32_t*)&C[r0 * N + cc] = pk_h2(o1, o2);
            cs = rope_t[(pos0 + 8) * 32 + p];
            o1 = (acc[f][n][2] * cs.x - acc[f][n][3] * cs.y) * qs;
            o2 = (acc[f][n][2] * cs.y + acc[f][n][3] * cs.x) * qs;
            *(uint32_t*)&C[(r0 + 8) * N + cc] = pk_h2(o1, o2);
        }
    }
}

// ===========================================================================
// RoPE table. sincos(x, SIN, COS) — sin first!
// ===========================================================================
__global__ void rope_table_kernel(float2* __restrict__ t) {
    int i = blockIdx.x * blockDim.x + threadIdx.x;
    int p = i & 31;
    int s = i >> 5;
    double inv = exp(-(double)p * (log(10000.0) / 32.0));
    double a = (double)s * inv;
    double sd, cd;
    sincos(a, &sd, &cd);
    t[i] = make_float2((float)cd, (float)sd);
}

// ===========================================================================
// Prep: V -> transposed fp16  vt[b][h][d][s]
// ===========================================================================
__global__ __launch_bounds__(256) void prep_vth(const float* __restrict__ vp,
                                                __half* __restrict__ vt) {
    __shared__ float sm[64][65];
    const int tid = threadIdx.x;
    const int st = blockIdx.x, h = blockIdx.y, b = blockIdx.z;

    for (int i = tid; i < 1024; i += 256) {
        int r = i >> 4;
        int f4 = (i & 15) * 4;
        float4 v = *(const float4*)&vp[(size_t)(b * S_ + st * 64 + r) * DE + h * DH + f4];
        sm[r][f4] = v.x; sm[r][f4 + 1] = v.y; sm[r][f4 + 2] = v.z; sm[r][f4 + 3] = v.w;
    }
    __syncthreads();

    const int d = tid >> 2;
    const int ks = (tid & 3) * 16;
    uint32_t pk[8];
#pragma unroll
    for (int j = 0; j < 8; j++)
        pk[j] = pk_h2(sm[ks + 2 * j][d], sm[ks + 2 * j + 1][d]);

    __half* dh = vt + ((size_t)((b * NH + h) * DH + d)) * S_ + st * 64 + ks;
    *(uint4*)&dh[0] = make_uint4(pk[0], pk[1], pk[2], pk[3]);
    *(uint4*)&dh[8] = make_uint4(pk[4], pk[5], pk[6], pk[7]);
}

// ===========================================================================
// fp16 tensor-core causal flash attention (round-14/16, PASS — unchanged)
// ===========================================================================
#define AP 72
#define STGE (128 * AP)
#define ATTN_SMEM (3 * STGE * 2)

__global__ __launch_bounds__(256) void attn_hf(
    const __half* __restrict__ qf, const __half* __restrict__ kf,
    const __half* __restrict__ vt, __half* __restrict__ af) {
    extern __shared__ __align__(16) __half sm[];

    const int tid = threadIdx.x;
    const int w = tid >> 5;
    const int lane = tid & 31;
    const int b = blockIdx.z, h = blockIdx.y;
    const int q0 = blockIdx.x * 128;
    const uint32_t smb = smem_u32(sm);
    const int nkt = 2 * blockIdx.x + 2;

    const __half* Kf = kf + (size_t)b * S_ * DE + h * DH;
    const __half* Vt = vt + (size_t)(b * NH + h) * DH * S_;

    const int cr = tid >> 3;
    const int csg = tid & 7;

    auto issue = [&](int k0, int s) {
        const uint32_t base = smb + (uint32_t)s * STGE * 2;
#pragma unroll
        for (int j = 0; j < 2; j++) {
            int r = cr + 32 * j;
            uint32_t dof = ((uint32_t)r * AP + csg * 8) * 2;
            cp16(base + dof, Kf + (size_t)(k0 + r) * DE + csg * 8);
            cp16(base + 64 * AP * 2 + dof, Vt + (size_t)r * S_ + k0 + csg * 8);
        }
        CP_COMMIT();
    };

    issue(0, 0);
    if (nkt > 1) issue(64, 1);

    {
        __half* qsm = sm + 2 * STGE;
        const __half* sh = qf + (size_t)(b * S_ + q0) * DE + h * DH;
#pragma unroll
        for (int j = 0; j < 4; j++) {
            int i = tid + 256 * j;
            int r = i >> 3, sg = i & 7;
            *(uint4*)&qsm[r * AP + sg * 8] = *(const uint4*)&sh[(size_t)r * DE + sg * 8];
        }
    }
    __syncthreads();

    uint32_t qfr[4][4];
    {
        const uint32_t qb = smb + 2 * STGE * 2;
        const int arow = w * 16 + (lane & 15);
        const int ak8 = (lane >> 4) << 3;
#pragma unroll
        for (int kc = 0; kc < 4; kc++)
            ldm4(qfr[kc], qb + (uint32_t)(arow * AP + kc * 16 + ak8) * 2);
    }
    __syncthreads();

    float oacc[8][4];
#pragma unroll
    for (int n = 0; n < 8; n++)
#pragma unroll
        for (int i = 0; i < 4; i++) oacc[n][i] = 0.f;
    float m0 = -1e30f, m1 = -1e30f, l0 = 0.f, l1 = 0.f;

    const int row0 = q0 + w * 16 + (lane >> 2);
    const int brow = (lane & 7) + ((lane & 16) ? 8 : 0);
    const int bk8 = (lane & 8) ? 8 : 0;

    int bufsel = 0;
    for (int kt = 0; kt < nkt; kt++) {
        const int k0 = kt * 64;
        if (kt + 2 < nkt) { CP_WAIT(1); } else { CP_WAIT(0); }
        __syncthreads();
        if (kt + 2 < nkt) {
            int nb = bufsel + 2;
            if (nb >= 3) nb -= 3;
            issue(k0 + 128, nb);
        }

        const uint32_t kb = smb + (uint32_t)bufsel * STGE * 2;

        float sacc[8][4];
#pragma unroll
        for (int n = 0; n < 8; n++)
#pragma unroll
            for (int i = 0; i < 4; i++) sacc[n][i] = 0.f;

#pragma unroll
        for (int kc = 0; kc < 4; kc++)
#pragma unroll
            for (int g = 0; g < 4; g++) {
                uint32_t off = (uint32_t)((g * 16 + brow) * AP + kc * 16 + bk8) * 2;
                uint32_t t[4];
                ldm4(t, kb + off);
                uint32_t b0[2] = {t[0], t[1]}, b1[2] = {t[2], t[3]};
                mma16816h(sacc[2 * g], qfr[kc], b0);
                mma16816h(sacc[2 * g + 1], qfr[kc], b1);
            }

        if (kt >= nkt - 2) {
#pragma unroll
            for (int n = 0; n < 8; n++) {
                int col = k0 + n * 8 + (lane & 3) * 2;
                if (col > row0) sacc[n][0] = -1e30f;
                if (col + 1 > row0) sacc[n][1] = -1e30f;
                if (col > row0 + 8) sacc[n][2] = -1e30f;
                if (col + 1 > row0 + 8) sacc[n][3] = -1e30f;
            }
        }

        float mt0 = -1e30f, mt1 = -1e30f;
#pragma unroll
        for (int n = 0; n < 8; n++) {
            mt0 = fmaxf(mt0, fmaxf(sacc[n][0], sacc[n][1]));
            mt1 = fmaxf(mt1, fmaxf(sacc[n][2], sacc[n][3]));
        }
        mt0 = fmaxf(mt0, __shfl_xor_sync(0xffffffffu, mt0, 1));
        mt0 = fmaxf(mt0, __shfl_xor_sync(0xffffffffu, mt0, 2));
        mt1 = fmaxf(mt1, __shfl_xor_sync(0xffffffffu, mt1, 1));
        mt1 = fmaxf(mt1, __shfl_xor_sync(0xffffffffu, mt1, 2));

        float mn0 = fmaxf(m0, mt0), mn1 = fmaxf(m1, mt1);
        float a0 = __expf(m0 - mn0), a1 = __expf(m1 - mn1);
        m0 = mn0; m1 = mn1;

        float s0 = 0.f, s1 = 0.f;
#pragma unroll
        for (int n = 0; n < 8; n++) {
            sacc[n][0] = __expf(sacc[n][0] - mn0);
            sacc[n][1] = __expf(sacc[n][1] - mn0);
            sacc[n][2] = __expf(sacc[n][2] - mn1);
            sacc[n][3] = __expf(sacc[n][3] - mn1);
            s0 += sacc[n][0] + sacc[n][1];
            s1 += sacc[n][2] + sacc[n][3];
        }
        s0 += __shfl_xor_sync(0xffffffffu, s0, 1);
        s0 += __shfl_xor_sync(0xffffffffu, s0, 2);
        s1 += __shfl_xor_sync(0xffffffffu, s1, 1);
        s1 += __shfl_xor_sync(0xffffffffu, s1, 2);
        l0 = l0 * a0 + s0;
        l1 = l1 * a1 + s1;
#pragma unroll
        for (int n = 0; n < 8; n++) {
            oacc[n][0] *= a0; oacc[n][1] *= a0;
            oacc[n][2] *= a1; oacc[n][3] *= a1;
        }

#pragma unroll
        for (int kc = 0; kc < 4; kc++) {
            uint32_t pa[4];
            pa[0] = pk_h2(sacc[2 * kc][0], sacc[2 * kc][1]);
            pa[1] = pk_h2(sacc[2 * kc][2], sacc[2 * kc][3]);
            pa[2] = pk_h2(sacc[2 * kc + 1][0], sacc[2 * kc + 1][1]);
            pa[3] = pk_h2(sacc[2 * kc + 1][2], sacc[2 * kc + 1][3]);
#pragma unroll
            for (int g = 0; g < 4; g++) {
                uint32_t off = (uint32_t)((64 + g * 16 + brow) * AP + kc * 16 + bk8) * 2;
                uint32_t t[4];
                ldm4(t, kb + off);
                uint32_t b0[2] = {t[0], t[1]}, b1[2] = {t[2], t[3]};
                mma16816h(oacc[2 * g], pa, b0);
                mma16816h(oacc[2 * g + 1], pa, b1);
            }
        }

        if (++bufsel == 3) bufsel = 0;
    }

    const float inv0 = 1.0f / l0, inv1 = 1.0f / l1;
    const size_t gr0 = (size_t)(b * S_ + row0);
#pragma unroll
    for (int n = 0; n < 8; n++) {
        const size_t cc = (size_t)(h * DH + n * 8 + (lane & 3) * 2);
        *(uint32_t*)&af[gr0 * DE + cc] = pk_h2(oacc[n][0] * inv0, oacc[n][1] * inv0);
        *(uint32_t*)&af[(gr0 + 8) * DE + cc] = pk_h2(oacc[n][2] * inv1, oacc[n][3] * inv1);
    }
}

// ===========================================================================
extern "C" void kernel_launch(void* const* d_in, const int* in_sizes, int n_in,
                              void* d_out, int out_size) {
    const float* q  = (const float*)d_in[0];
    const float* k  = (const float*)d_in[1];
    const float* v  = (const float*)d_in[2];
    const float* Wq = (const float*)d_in[3];
    const float* Wk = (const float*)d_in[4];
    const float* Wv = (const float*)d_in[5];
    const float* Wo = (const float*)d_in[6];
    float* out = (float*)d_out;

    float* vp;
    float2* rope_t;
    __half *qf, *kf, *vt, *af, *wf;
    cudaGetSymbolAddress((void**)&vp, g_vp);
    cudaGetSymbolAddress((void**)&rope_t, g_rope);
    cudaGetSymbolAddress((void**)&qf, g_qf2);
    cudaGetSymbolAddress((void**)&kf, g_kf2);
    cudaGetSymbolAddress((void**)&vt, g_vt2);
    cudaGetSymbolAddress((void**)&af, g_af);
    cudaGetSymbolAddress((void**)&wf, g_wf);

    cudaFuncSetAttribute(attn_hf, cudaFuncAttributeMaxDynamicSharedMemorySize,
                         ATTN_SMEM);
    cudaFuncSetAttribute(gemm_hf, cudaFuncAttributeMaxDynamicSharedMemorySize,
                         GEMM_SMEM);
    cudaFuncSetAttribute(gemm_qk, cudaFuncAttributeMaxDynamicSharedMemorySize,
                         GEMM_SMEM);

    rope_table_kernel<<<(S_ * 32) / 256, 256>>>(rope_t);

    const int n_qk = BSROWS * 2 * DE;
    const int n_v  = BSROWS * DE;
    const int n_w2 = DE * 2 * DE;
    const int n_w1 = DE * DE;
    dim3 gq(DE / 128, BSROWS / 128);       // (8, 64)

    // Q projection (+ fused RoPE, prescale 1/32, fp16 out)
    prep_h<<<n_w2 / 1024, 256>>>(Wq, wf, n_w2 / 4);
    prep_h<<<n_qk / 1024, 256>>>(q, af, n_qk / 4);
    gemm_qk<<<gq, 256, GEMM_SMEM>>>(af, wf, qf, rope_t, 0.03125f, BSROWS, DE, 2 * DE);
    // K projection (+ fused RoPE, fp16 out)
    prep_h<<<n_w2 / 1024, 256>>>(Wk, wf, n_w2 / 4);
    prep_h<<<n_qk / 1024, 256>>>(k, af, n_qk / 4);
    gemm_qk<<<gq, 256, GEMM_SMEM>>>(af, wf, kf, rope_t, 1.0f, BSROWS, DE, 2 * DE);
    // V projection (fp32 out for transpose prep)
    prep_h<<<n_w1 / 1024, 256>>>(Wv, wf, n_w1 / 4);
    prep_h<<<n_v / 1024, 256>>>(v, af, n_v / 4);
    gemm_hf<<<gq, 256, GEMM_SMEM>>>(af, wf, vp, BSROWS, DE, DE);

    prep_vth<<<dim3(S_ / 64, NH, B_), 256>>>(vp, vt);

    attn_hf<<<dim3(S_ / 128, NH, B_), 256, ATTN_SMEM>>>(qf, kf, vt, af);

    // Output projection
    prep_h<<<n_w1 / 1024, 256>>>(Wo, wf, n_w1 / 4);
    gemm_hf<<<gq, 256, GEMM_SMEM>>>(af, wf, out, BSROWS, DE, DE);
}